// round 1
// baseline (speedup 1.0000x reference)
#include <cuda_runtime.h>
#include <math.h>
#include <stdint.h>

// Input order (metadata.txt):
// 0 v_data f32[524288*16], 1 cond f32[524288], 2 W f32[16*32], 3 b f32[16],
// 4 c f32[32], 5 W1 f32[64], 6 b1 f32[64], 7 W2 f32[64*96], 8 b2 f32[96], 9 k int[1]
// output: f32[1] (scalar loss)

#define NV 16
#define NH 32
#define TPB 256
#define MAXK 64
#define MAXBLK 4096

__device__ float g_M[64 * 48];     // folded MLP->mod matrix
__device__ float g_base[48];       // folded bias part of mods
__device__ uint2 g_k1[MAXK];       // per-step bernoulli key for hidden draws
__device__ uint2 g_k2[MAXK];       // per-step bernoulli key for visible draws
__device__ float g_part[MAXBLK];   // per-block partial sums

// ---------------------------------------------------------------------------
// threefry2x32 (JAX/Random123 constants)
// ---------------------------------------------------------------------------
__device__ __forceinline__ uint32_t rotl32(uint32_t x, int r) {
    return __funnelshift_l(x, x, r);
}

__device__ __forceinline__ void tf_core(uint32_t& x0, uint32_t& x1,
                                        uint32_t k0, uint32_t k1, uint32_t k2) {
#define TFR(r) { x0 += x1; x1 = rotl32(x1, r); x1 ^= x0; }
    TFR(13) TFR(15) TFR(26) TFR(6)   x0 += k1; x1 += k2 + 1u;
    TFR(17) TFR(29) TFR(16) TFR(24)  x0 += k2; x1 += k0 + 2u;
    TFR(13) TFR(15) TFR(26) TFR(6)   x0 += k0; x1 += k1 + 3u;
    TFR(17) TFR(29) TFR(16) TFR(24)  x0 += k1; x1 += k2 + 4u;
    TFR(13) TFR(15) TFR(26) TFR(6)   x0 += k2; x1 += k0 + 5u;
#undef TFR
}

__device__ __forceinline__ uint2 tf2x32(uint2 key, uint32_t chi, uint32_t clo) {
    uint32_t k2 = key.x ^ key.y ^ 0x1BD11BDAu;
    uint32_t x0 = chi + key.x;
    uint32_t x1 = clo + key.y;
    tf_core(x0, x1, key.x, key.y, k2);
    return make_uint2(x0, x1);
}

// JAX partitionable 32-bit random bits for flat element index idx (< 2^32):
// counter = (hi=0, lo=idx); 32-bit output combines the two halves via XOR.
__device__ __forceinline__ uint32_t tf_bits32(uint2 key, uint32_t idx) {
    uint2 r = tf2x32(key, 0u, idx);
    return r.x ^ r.y;
}

// JAX uniform[0,1): (bits>>9)|0x3f800000 bitcast -> [1,2), minus 1
__device__ __forceinline__ float u01(uint32_t bits) {
    return __uint_as_float((bits >> 9) | 0x3f800000u) - 1.0f;
}

// jax.nn.softplus = logaddexp(x, 0) = max(x,0) + log1p(exp(-|x|))
__device__ __forceinline__ float softplusf(float x) {
    return fmaxf(x, 0.0f) + log1pf(expf(-fabsf(x)));
}

// fast sigmoid for bernoulli thresholds (error ~5e-7 -> negligible flip rate)
__device__ __forceinline__ float sigmoidf_fast(float x) {
    return __fdividef(1.0f, 1.0f + __expf(-x));
}

// ---------------------------------------------------------------------------
// init kernel: key-split chain + folded modulation matrices
//   b_mod[i] = base[i]    + sum_j t_j * M[j][i]       (i in 0..15)
//   c_mod[l] = base[16+l] + sum_j t_j * M[j][16+l]    (l in 0..31)
// where M[j][i]    = b[i]*W2[j][i]    + W2[j][16+i]
//       M[j][16+l] = c[l]*W2[j][32+l] + W2[j][64+l]
//       base[i]    = b[i]*(1+b2[i])    + b2[16+i]
//       base[16+l] = c[l]*(1+b2[32+l]) + b2[64+l]
// ---------------------------------------------------------------------------
__global__ void rbm_init_kernel(const float* __restrict__ W2,
                                const float* __restrict__ bias_b,
                                const float* __restrict__ bias_c,
                                const float* __restrict__ b2,
                                const int* __restrict__ kp) {
    int t = threadIdx.x;
    for (int idx = t; idx < 64 * 48; idx += blockDim.x) {
        int j = idx / 48, q = idx % 48;
        float m;
        if (q < NV) {
            m = bias_b[q] * W2[j * 96 + q] + W2[j * 96 + 16 + q];
        } else {
            int l = q - NV;
            m = bias_c[l] * W2[j * 96 + 32 + l] + W2[j * 96 + 64 + l];
        }
        g_M[idx] = m;
    }
    if (t < 48) {
        float bs;
        if (t < NV) bs = bias_b[t] * (1.0f + b2[t]) + b2[16 + t];
        else {
            int l = t - NV;
            bs = bias_c[l] * (1.0f + b2[32 + l]) + b2[64 + l];
        }
        g_base[t] = bs;
    }
    if (t == 0) {
        int kk = *kp;
        if (kk < 0) kk = 0;
        if (kk > MAXK) kk = MAXK;
        // chain: key = key(42) = (0, 42); each step: key,k1,k2 = split(key,3)
        // partitionable split: subkey_i = threefry(key, counter=(0, i))
        uint2 key = make_uint2(0u, 42u);
        for (int s = 0; s < kk; ++s) {
            uint2 nk = tf2x32(key, 0u, 0u);
            g_k1[s] = tf2x32(key, 0u, 1u);
            g_k2[s] = tf2x32(key, 0u, 2u);
            key = nk;
        }
    }
}

// ---------------------------------------------------------------------------
// main kernel: one sample per thread
// ---------------------------------------------------------------------------
__device__ __forceinline__ float free_energy(const float* v, const float* mod,
                                             const float* sWt) {
    float e = 0.0f;
#pragma unroll
    for (int i = 0; i < NV; ++i) e = fmaf(v[i], mod[i], e);
    float esp = 0.0f;
#pragma unroll 4
    for (int j = 0; j < NH; ++j) {
        float s = mod[NV + j];
        const float4* w4 = reinterpret_cast<const float4*>(sWt + j * NV);
#pragma unroll
        for (int r = 0; r < 4; ++r) {
            float4 w = w4[r];
            s = fmaf(v[r * 4 + 0], w.x, s);
            s = fmaf(v[r * 4 + 1], w.y, s);
            s = fmaf(v[r * 4 + 2], w.z, s);
            s = fmaf(v[r * 4 + 3], w.w, s);
        }
        esp += softplusf(s);
    }
    return -e - esp;
}

__global__ void __launch_bounds__(TPB)
rbm_main_kernel(const float* __restrict__ v_data,
                const float* __restrict__ cond,
                const float* __restrict__ W,
                const float* __restrict__ W1,
                const float* __restrict__ b1,
                const int* __restrict__ kp,
                int batch) {
    __shared__ float sWt[NH * NV];    // W transposed: sWt[j*16+i] = W[i][j]
    __shared__ float sM[64 * 48];
    __shared__ float sBase[48];
    __shared__ float sW1[64];
    __shared__ float sb1[64];
    __shared__ uint2 sk1[MAXK];
    __shared__ uint2 sk2[MAXK];

    int t = threadIdx.x;
    for (int idx = t; idx < NH * NV; idx += TPB) {
        int j = idx / NV, i = idx % NV;
        sWt[idx] = W[i * NH + j];
    }
    for (int idx = t; idx < 64 * 48; idx += TPB) sM[idx] = g_M[idx];
    if (t < 48) sBase[t] = g_base[t];
    if (t < 64) {
        sW1[t] = W1[t];
        sb1[t] = b1[t];
        sk1[t] = g_k1[t];
        sk2[t] = g_k2[t];
    }
    __syncthreads();

    int sample = blockIdx.x * TPB + t;
    if (sample >= batch) { // still participate in reduction with 0
        // fallthrough with zero loss
    }
    bool active = sample < batch;
    float loss = 0.0f;

    if (active) {
        // ---- conditioning MLP (folded) ----
        float cb = cond[sample];
        float mod[48];
#pragma unroll
        for (int q = 0; q < 48; ++q) mod[q] = sBase[q];
#pragma unroll 2
        for (int j = 0; j < 64; ++j) {
            float tj = tanhf(fmaf(cb, sW1[j], sb1[j]));
            const float4* m4 = reinterpret_cast<const float4*>(&sM[j * 48]);
#pragma unroll
            for (int q4 = 0; q4 < 12; ++q4) {
                float4 m = m4[q4];
                mod[q4 * 4 + 0] = fmaf(tj, m.x, mod[q4 * 4 + 0]);
                mod[q4 * 4 + 1] = fmaf(tj, m.y, mod[q4 * 4 + 1]);
                mod[q4 * 4 + 2] = fmaf(tj, m.z, mod[q4 * 4 + 2]);
                mod[q4 * 4 + 3] = fmaf(tj, m.w, mod[q4 * 4 + 3]);
            }
        }

        // ---- load v_data ----
        float v[NV];
        const float4* vd = reinterpret_cast<const float4*>(v_data + (size_t)sample * NV);
#pragma unroll
        for (int r = 0; r < 4; ++r) {
            float4 x = vd[r];
            v[r * 4 + 0] = x.x; v[r * 4 + 1] = x.y;
            v[r * 4 + 2] = x.z; v[r * 4 + 3] = x.w;
        }

        float fe_data = free_energy(v, mod, sWt);

        // ---- Gibbs chain ----
        int kk = *kp;
        if (kk < 0) kk = 0;
        if (kk > MAXK) kk = MAXK;
        uint32_t base_h = (uint32_t)sample * NH;
        uint32_t base_v = (uint32_t)sample * NV;

        for (int s = 0; s < kk; ++s) {
            uint2 key1 = sk1[s];
            uint2 key2 = sk2[s];
            float acc[NV];
#pragma unroll
            for (int i = 0; i < NV; ++i) acc[i] = 0.0f;

#pragma unroll 4
            for (int j = 0; j < NH; ++j) {
                float w[NV];
                const float4* w4 = reinterpret_cast<const float4*>(&sWt[j * NV]);
#pragma unroll
                for (int r = 0; r < 4; ++r) {
                    float4 x = w4[r];
                    w[r * 4 + 0] = x.x; w[r * 4 + 1] = x.y;
                    w[r * 4 + 2] = x.z; w[r * 4 + 3] = x.w;
                }
                float sj = mod[NV + j];
#pragma unroll
                for (int i = 0; i < NV; ++i) sj = fmaf(v[i], w[i], sj);
                float p = sigmoidf_fast(sj);
                float u = u01(tf_bits32(key1, base_h + (uint32_t)j));
                float h = (u < p) ? 1.0f : 0.0f;
#pragma unroll
                for (int i = 0; i < NV; ++i) acc[i] = fmaf(h, w[i], acc[i]);
            }
#pragma unroll 4
            for (int i = 0; i < NV; ++i) {
                float sv = acc[i] + mod[i];
                float p = sigmoidf_fast(sv);
                float u = u01(tf_bits32(key2, base_v + (uint32_t)i));
                v[i] = (u < p) ? 1.0f : 0.0f;
            }
        }

        float fe_model = free_energy(v, mod, sWt);
        loss = fe_data - fe_model;
    }

    // ---- deterministic block reduction (fixed-order trees) ----
#pragma unroll
    for (int off = 16; off > 0; off >>= 1)
        loss += __shfl_down_sync(0xffffffffu, loss, off);

    __shared__ float swarp[TPB / 32];
    if ((t & 31) == 0) swarp[t >> 5] = loss;
    __syncthreads();
    if (t == 0) {
        float tot = 0.0f;
#pragma unroll
        for (int wgi = 0; wgi < TPB / 32; ++wgi) tot += swarp[wgi];
        g_part[blockIdx.x] = tot;
    }
}

__global__ void rbm_finish_kernel(float* __restrict__ out, int nblocks, int batch) {
    __shared__ double sd[256];
    int t = threadIdx.x;
    double s = 0.0;
    for (int idx = t; idx < nblocks; idx += 256) s += (double)g_part[idx];
    sd[t] = s;
    __syncthreads();
    for (int off = 128; off > 0; off >>= 1) {
        if (t < off) sd[t] += sd[t + off];
        __syncthreads();
    }
    if (t == 0) out[0] = (float)(sd[0] / (double)batch);
}

// ---------------------------------------------------------------------------
extern "C" void kernel_launch(void* const* d_in, const int* in_sizes, int n_in,
                              void* d_out, int out_size) {
    const float* v_data = (const float*)d_in[0];
    const float* cond   = (const float*)d_in[1];
    const float* W      = (const float*)d_in[2];
    const float* bias_b = (const float*)d_in[3];
    const float* bias_c = (const float*)d_in[4];
    const float* W1     = (const float*)d_in[5];
    const float* b1     = (const float*)d_in[6];
    const float* W2     = (const float*)d_in[7];
    const float* b2     = (const float*)d_in[8];
    const int*   kp     = (const int*)d_in[9];

    int batch = in_sizes[0] / NV;   // 524288
    int nblocks = (batch + TPB - 1) / TPB;
    if (nblocks > MAXBLK) nblocks = MAXBLK;  // problem size is fixed; guard

    rbm_init_kernel<<<1, 256>>>(W2, bias_b, bias_c, b2, kp);
    rbm_main_kernel<<<nblocks, TPB>>>(v_data, cond, W, W1, b1, kp, batch);
    rbm_finish_kernel<<<1, 256>>>((float*)d_out, nblocks, batch);
}

// round 2
// speedup vs baseline: 1.2043x; 1.2043x over previous
#include <cuda_runtime.h>
#include <stdint.h>
#include <math.h>

// Inputs: 0 v_data f32[524288*16], 1 cond f32[524288], 2 W f32[16*32], 3 b f32[16],
// 4 c f32[32], 5 W1 f32[64], 6 b1 f32[64], 7 W2 f32[64*96], 8 b2 f32[96], 9 k int[1]
// output: f32[1]

#define NV 16
#define NH 32
#define TPB 128
#define MAXK 64
#define MAXBLK 8192

__device__ float g_part[MAXBLK];
__device__ unsigned int g_ticket;   // zero-init; reset by last block each launch

// ---------------------------------------------------------------------------
// threefry2x32 (JAX partitionable semantics, verified bit-exact in R1)
// ---------------------------------------------------------------------------
__device__ __forceinline__ uint32_t rotl32(uint32_t x, int r) {
    return __funnelshift_l(x, x, r);
}

__device__ __forceinline__ uint2 tf2x32(uint2 key, uint32_t chi, uint32_t clo) {
    uint32_t k0 = key.x, k1 = key.y, k2 = k0 ^ k1 ^ 0x1BD11BDAu;
    uint32_t x0 = chi + k0, x1 = clo + k1;
#define TFR(r) { x0 += x1; x1 = rotl32(x1, r); x1 ^= x0; }
    TFR(13) TFR(15) TFR(26) TFR(6)   x0 += k1; x1 += k2 + 1u;
    TFR(17) TFR(29) TFR(16) TFR(24)  x0 += k2; x1 += k0 + 2u;
    TFR(13) TFR(15) TFR(26) TFR(6)   x0 += k0; x1 += k1 + 3u;
    TFR(17) TFR(29) TFR(16) TFR(24)  x0 += k1; x1 += k2 + 4u;
    TFR(13) TFR(15) TFR(26) TFR(6)   x0 += k2; x1 += k0 + 5u;
#undef TFR
    return make_uint2(x0, x1);
}

// per-step hoisted key material (injection constants precomputed once/step)
struct TFK { uint32_t k0, k1, k2, c1, c2, c3, c4, c5; };

__device__ __forceinline__ TFK mk_tfk(uint2 key) {
    TFK K;
    K.k0 = key.x; K.k1 = key.y; K.k2 = K.k0 ^ K.k1 ^ 0x1BD11BDAu;
    K.c1 = K.k2 + 1u; K.c2 = K.k0 + 2u; K.c3 = K.k1 + 3u;
    K.c4 = K.k2 + 4u; K.c5 = K.k0 + 5u;
    return K;
}

__device__ __forceinline__ uint32_t tf_bits(const TFK K, uint32_t idx) {
    uint32_t x0 = K.k0, x1 = idx + K.k1;
#define TFR(r) { x0 += x1; x1 = rotl32(x1, r); x1 ^= x0; }
    TFR(13) TFR(15) TFR(26) TFR(6)   x0 += K.k1; x1 += K.c1;
    TFR(17) TFR(29) TFR(16) TFR(24)  x0 += K.k2; x1 += K.c2;
    TFR(13) TFR(15) TFR(26) TFR(6)   x0 += K.k0; x1 += K.c3;
    TFR(17) TFR(29) TFR(16) TFR(24)  x0 += K.k1; x1 += K.c4;
    TFR(13) TFR(15) TFR(26) TFR(6)   x0 += K.k2; x1 += K.c5;
#undef TFR
    return x0 ^ x1;
}

__device__ __forceinline__ float u01(uint32_t bits) {
    return __uint_as_float((bits >> 9) | 0x3f800000u) - 1.0f;
}
__device__ __forceinline__ float sigmoidf_fast(float x) {
    return __fdividef(1.0f, 1.0f + __expf(-x));
}
__device__ __forceinline__ float softplusf(float x) {
    return fmaxf(x, 0.0f) + log1pf(expf(-fabsf(x)));
}

// packed fp32x2 helpers (bit-identical per-lane rounding)
__device__ __forceinline__ void ffma2(unsigned long long& a, unsigned long long b,
                                      unsigned long long c) {
    asm("fma.rn.f32x2 %0, %1, %2, %0;" : "+l"(a) : "l"(b), "l"(c));
}
__device__ __forceinline__ unsigned long long dup2(float h) {
    unsigned long long r;
    asm("mov.b64 %0, {%1, %1};" : "=l"(r) : "r"(__float_as_uint(h)));
    return r;
}
__device__ __forceinline__ unsigned long long pack2(float a, float b) {
    unsigned long long r;
    asm("mov.b64 %0, {%1, %2};" : "=l"(r) : "r"(__float_as_uint(a)), "r"(__float_as_uint(b)));
    return r;
}
__device__ __forceinline__ float lo32f(unsigned long long v) {
    return __uint_as_float((uint32_t)v);
}
__device__ __forceinline__ float hi32f(unsigned long long v) {
    return __uint_as_float((uint32_t)(v >> 32));
}

union F4U { float4 f; unsigned long long u[2]; };

// ---------------------------------------------------------------------------
// free energy: -(v.b_mod) - sum_j softplus(v.W_j + c_mod_j)
// b_mod in registers (packed pairs), c_mod in smem column (stride TPB)
// ---------------------------------------------------------------------------
__device__ __forceinline__ float free_energy(const float v[NV],
                                             const unsigned long long bmod[8],
                                             const float* scmod_col,
                                             const float* sWt) {
    float e = 0.0f;
#pragma unroll
    for (int p = 0; p < 8; ++p) {
        e = fmaf(v[2 * p],     lo32f(bmod[p]), e);
        e = fmaf(v[2 * p + 1], hi32f(bmod[p]), e);
    }
    float esp = 0.0f;
#pragma unroll 4
    for (int j = 0; j < NH; ++j) {
        float s = scmod_col[j * TPB];
        const float4* w4 = reinterpret_cast<const float4*>(sWt + j * NV);
#pragma unroll
        for (int r = 0; r < 4; ++r) {
            float4 w = w4[r];
            s = fmaf(v[r * 4 + 0], w.x, s);
            s = fmaf(v[r * 4 + 1], w.y, s);
            s = fmaf(v[r * 4 + 2], w.z, s);
            s = fmaf(v[r * 4 + 3], w.w, s);
        }
        esp += softplusf(s);
    }
    return -e - esp;
}

// ---------------------------------------------------------------------------
// single fused kernel
// ---------------------------------------------------------------------------
__global__ void __launch_bounds__(TPB)
rbm_fused(const float* __restrict__ v_data,
          const float* __restrict__ cond,
          const float* __restrict__ W,
          const float* __restrict__ bias_b,
          const float* __restrict__ bias_c,
          const float* __restrict__ W1,
          const float* __restrict__ b1,
          const float* __restrict__ W2,
          const float* __restrict__ b2,
          const int* __restrict__ kp,
          float* __restrict__ out,
          int batch) {
    __shared__ __align__(16) float sWt[NH * NV];   // W^T: sWt[j*16+i]
    __shared__ __align__(16) float sM[64 * 48];    // folded MLP matrix
    __shared__ float sBase[48];
    __shared__ float sW1[64], sb1[64];
    __shared__ uint2 sck[MAXK];
    __shared__ uint2 sk1[MAXK], sk2[MAXK];
    __shared__ int   skk;
    __shared__ float scmod[NH * TPB];              // c_mod per thread, 16KB
    __shared__ float swarp[TPB / 32];
    __shared__ int   sIsLast;
    __shared__ double sd[TPB];

    const int t = threadIdx.x;

    // ---- per-block init (redundant across blocks; cheap) ----
    for (int idx = t; idx < NH * NV; idx += TPB) {
        int j = idx / NV, i = idx % NV;
        sWt[idx] = W[i * NH + j];
    }
    for (int idx = t; idx < 64 * 48; idx += TPB) {
        int j = idx / 48, q = idx % 48;
        float m;
        if (q < NV) {
            m = bias_b[q] * W2[j * 96 + q] + W2[j * 96 + 16 + q];
        } else {
            int l = q - NV;
            m = bias_c[l] * W2[j * 96 + 32 + l] + W2[j * 96 + 64 + l];
        }
        sM[idx] = m;
    }
    if (t < 48) {
        float bs;
        if (t < NV) bs = bias_b[t] * (1.0f + b2[t]) + b2[16 + t];
        else {
            int l = t - NV;
            bs = bias_c[l] * (1.0f + b2[32 + l]) + b2[64 + l];
        }
        sBase[t] = bs;
    }
    if (t < 64) { sW1[t] = W1[t]; sb1[t] = b1[t]; }
    if (t == 0) {
        int kkv = *kp;
        if (kkv < 0) kkv = 0;
        if (kkv > MAXK) kkv = MAXK;
        skk = kkv;
        uint2 key = make_uint2(0u, 42u);
        for (int s = 0; s < kkv; ++s) {
            sck[s] = key;
            key = tf2x32(key, 0u, 0u);
        }
    }
    __syncthreads();
    const int kk = skk;
    if (t < kk)                      sk1[t]      = tf2x32(sck[t],      0u, 1u);
    else if (t >= 64 && t < 64 + kk) sk2[t - 64] = tf2x32(sck[t - 64], 0u, 2u);
    __syncthreads();

    // ---- per-sample work ----
    const int sample = blockIdx.x * TPB + t;
    float loss = 0.0f;

    if (sample < batch) {
        // conditioning MLP (folded), packed fp32x2 accumulate
        float cb = cond[sample];
        unsigned long long modp[24];
#pragma unroll
        for (int q = 0; q < 24; ++q) modp[q] = pack2(sBase[2 * q], sBase[2 * q + 1]);
        const unsigned long long* sM2 = reinterpret_cast<const unsigned long long*>(sM);
#pragma unroll 4
        for (int j = 0; j < 64; ++j) {
            float tj = tanhf(fmaf(cb, sW1[j], sb1[j]));
            unsigned long long tj2 = dup2(tj);
#pragma unroll
            for (int q = 0; q < 24; ++q) ffma2(modp[q], tj2, sM2[j * 24 + q]);
        }

        // b_mod stays in regs; c_mod to per-thread smem column (static access)
        unsigned long long bmod[8];
#pragma unroll
        for (int p = 0; p < 8; ++p) bmod[p] = modp[p];
        float* scmod_col = &scmod[t];
#pragma unroll
        for (int p = 0; p < 16; ++p) {
            scmod_col[(2 * p) * TPB]     = lo32f(modp[8 + p]);
            scmod_col[(2 * p + 1) * TPB] = hi32f(modp[8 + p]);
        }

        // load v_data
        float v[NV];
        {
            const float4* vd = reinterpret_cast<const float4*>(v_data + (size_t)sample * NV);
#pragma unroll
            for (int r = 0; r < 4; ++r) {
                float4 x = vd[r];
                v[r * 4 + 0] = x.x; v[r * 4 + 1] = x.y;
                v[r * 4 + 2] = x.z; v[r * 4 + 3] = x.w;
            }
        }

        float fe_data = free_energy(v, bmod, scmod_col, sWt);

        // Gibbs chain
        const uint32_t base_h = (uint32_t)sample * NH;
        const uint32_t base_v = (uint32_t)sample * NV;

        for (int s = 0; s < kk; ++s) {
            const TFK K1 = mk_tfk(sk1[s]);
            unsigned long long acc[8];
#pragma unroll
            for (int p = 0; p < 8; ++p) acc[p] = 0ull;

#pragma unroll 4
            for (int j = 0; j < NH; ++j) {
                float sj = scmod_col[j * TPB];
                const F4U* w4 = reinterpret_cast<const F4U*>(sWt + j * NV);
                F4U w0 = w4[0], w1 = w4[1], w2 = w4[2], w3 = w4[3];
                sj = fmaf(v[0],  w0.f.x, sj); sj = fmaf(v[1],  w0.f.y, sj);
                sj = fmaf(v[2],  w0.f.z, sj); sj = fmaf(v[3],  w0.f.w, sj);
                sj = fmaf(v[4],  w1.f.x, sj); sj = fmaf(v[5],  w1.f.y, sj);
                sj = fmaf(v[6],  w1.f.z, sj); sj = fmaf(v[7],  w1.f.w, sj);
                sj = fmaf(v[8],  w2.f.x, sj); sj = fmaf(v[9],  w2.f.y, sj);
                sj = fmaf(v[10], w2.f.z, sj); sj = fmaf(v[11], w2.f.w, sj);
                sj = fmaf(v[12], w3.f.x, sj); sj = fmaf(v[13], w3.f.y, sj);
                sj = fmaf(v[14], w3.f.z, sj); sj = fmaf(v[15], w3.f.w, sj);
                float p = sigmoidf_fast(sj);
                float u = u01(tf_bits(K1, base_h + (uint32_t)j));
                float h = (u < p) ? 1.0f : 0.0f;
                unsigned long long h2 = dup2(h);
                ffma2(acc[0], h2, w0.u[0]); ffma2(acc[1], h2, w0.u[1]);
                ffma2(acc[2], h2, w1.u[0]); ffma2(acc[3], h2, w1.u[1]);
                ffma2(acc[4], h2, w2.u[0]); ffma2(acc[5], h2, w2.u[1]);
                ffma2(acc[6], h2, w3.u[0]); ffma2(acc[7], h2, w3.u[1]);
            }

            const TFK K2 = mk_tfk(sk2[s]);
#pragma unroll
            for (int i = 0; i < NV; ++i) {
                float a  = (i & 1) ? hi32f(acc[i >> 1])  : lo32f(acc[i >> 1]);
                float bm = (i & 1) ? hi32f(bmod[i >> 1]) : lo32f(bmod[i >> 1]);
                float sv = a + bm;
                float pv = sigmoidf_fast(sv);
                float u = u01(tf_bits(K2, base_v + (uint32_t)i));
                v[i] = (u < pv) ? 1.0f : 0.0f;
            }
        }

        float fe_model = free_energy(v, bmod, scmod_col, sWt);
        loss = fe_data - fe_model;
    }

    // ---- deterministic block reduction ----
#pragma unroll
    for (int off = 16; off > 0; off >>= 1)
        loss += __shfl_down_sync(0xffffffffu, loss, off);
    if ((t & 31) == 0) swarp[t >> 5] = loss;
    __syncthreads();
    if (t == 0) {
        float tot = 0.0f;
#pragma unroll
        for (int wgi = 0; wgi < TPB / 32; ++wgi) tot += swarp[wgi];
        g_part[blockIdx.x] = tot;
        __threadfence();
        unsigned r = atomicAdd(&g_ticket, 1u);
        sIsLast = (r == gridDim.x - 1) ? 1 : 0;
    }
    __syncthreads();

    // ---- last block does the final deterministic reduction ----
    if (sIsLast) {
        __threadfence();
        double accd = 0.0;
        for (int idx = t; idx < (int)gridDim.x; idx += TPB)
            accd += (double)g_part[idx];
        sd[t] = accd;
        __syncthreads();
#pragma unroll
        for (int off = TPB / 2; off > 0; off >>= 1) {
            if (t < off) sd[t] += sd[t + off];
            __syncthreads();
        }
        if (t == 0) {
            out[0] = (float)(sd[0] / (double)batch);
            g_ticket = 0u;   // reset for next graph replay
        }
    }
}

// ---------------------------------------------------------------------------
extern "C" void kernel_launch(void* const* d_in, const int* in_sizes, int n_in,
                              void* d_out, int out_size) {
    const float* v_data = (const float*)d_in[0];
    const float* cond   = (const float*)d_in[1];
    const float* W      = (const float*)d_in[2];
    const float* bias_b = (const float*)d_in[3];
    const float* bias_c = (const float*)d_in[4];
    const float* W1     = (const float*)d_in[5];
    const float* b1     = (const float*)d_in[6];
    const float* W2     = (const float*)d_in[7];
    const float* b2     = (const float*)d_in[8];
    const int*   kp     = (const int*)d_in[9];

    int batch = in_sizes[0] / NV;   // 524288
    int grid = (batch + TPB - 1) / TPB;
    if (grid > MAXBLK) grid = MAXBLK;  // problem size fixed at 4096 blocks

    rbm_fused<<<grid, TPB>>>(v_data, cond, W, bias_b, bias_c, W1, b1, W2, b2,
                             kp, (float*)d_out, batch);
}